// round 11
// baseline (speedup 1.0000x reference)
#include <cuda_runtime.h>
#include <cstdint>

// Problem constants (fixed shapes): x = (8,32,256,256) fp32, K=3
#define PLANES 256            // B*C
#define H      256
#define W      256
#define HO     254
#define WO     254
#define N_ELEM (PLANES * H * W)     // 16,777,216
#define N32    (N_ELEM / 8)         // 32-byte units

// Hist config
#define HB 1024
#define HTH 256
#define HITER8 (N32 / (HB * HTH))   // 8 x 32-byte loads per thread (64 elems)

// Pool config
#define PTH 16                // output rows per block
#define PROWS (PTH + 2)       // input rows per block (18)
#define WP16 260              // u16 tile row stride (256 data + 4 pad)

// bin i lives at g_cnt_pad[i*32] (128 B stride -> spread across LTS slices).
// Zero-init at load; zeroed again by the last hist block each replay.
__device__ unsigned int g_cnt_pad[256 * 32];
__device__ unsigned int g_packed[256];   // (rank<<8)|value, rank = #{u: cnt[u]<cnt[v]}
__device__ unsigned int g_ticket;

// ---------------------------------------------------------------------------
// Kernel 1: 256-bin histogram, 16-bit packed shared counters (2 bins/word),
// bank == lane -> zero conflicts (measured ~92% of the 4 ATOMS/cyc/SM floor).
// Tail: the last-arriving block computes the RANK transform (exact-tie
// preserving, 8 bits) into g_packed, zeroes the scratch and the ticket.
// ---------------------------------------------------------------------------
__global__ void __launch_bounds__(HTH) hist_kernel(const float* __restrict__ x) {
    __shared__ unsigned int s_h[128 * 32];   // 16 KB
    __shared__ unsigned s_last;
    const int tid = threadIdx.x;
    #pragma unroll
    for (int i = tid; i < 128 * 32; i += HTH) s_h[i] = 0u;
    __syncthreads();

    const int lane = tid & 31;
    const unsigned long long* base =
        (const unsigned long long*)x + (size_t)blockIdx.x * (HTH * HITER8) * 4;

    #pragma unroll
    for (int j = 0; j < HITER8; j++) {
        unsigned long long u0, u1, u2, u3;
        const unsigned long long* p = base + (size_t)(j * HTH + tid) * 4;
        asm volatile("ld.global.nc.L2::evict_last.v4.b64 {%0,%1,%2,%3}, [%4];"
                     : "=l"(u0), "=l"(u1), "=l"(u2), "=l"(u3) : "l"(p));
        #pragma unroll
        for (int q = 0; q < 4; q++) {
            unsigned long long u = (q == 0) ? u0 : (q == 1) ? u1 : (q == 2) ? u2 : u3;
            int a = ((int)__uint_as_float((unsigned)u)) & 255;
            int b = ((int)__uint_as_float((unsigned)(u >> 32))) & 255;
            atomicAdd(&s_h[(a >> 1) * 32 + lane], 1u << ((a & 1) << 4));
            atomicAdd(&s_h[(b >> 1) * 32 + lane], 1u << ((b & 1) << 4));
        }
    }
    __syncthreads();

    if (tid < 128) {
        unsigned lo = 0, hi = 0;
        #pragma unroll
        for (int j = 0; j < 32; j++) {
            unsigned w = s_h[tid * 32 + ((j + lane) & 31)];
            lo += w & 0xFFFFu;
            hi += w >> 16;
        }
        atomicAdd(&g_cnt_pad[(2 * tid + 0) * 32], lo);   // RED, no return
        atomicAdd(&g_cnt_pad[(2 * tid + 1) * 32], hi);
    }

    // --- last-block tail: rank transform + scratch reset ---
    __threadfence();
    __syncthreads();
    if (tid == 0) s_last = (atomicAdd(&g_ticket, 1u) == (unsigned)(HB - 1)) ? 1u : 0u;
    __syncthreads();
    if (s_last) {
        __threadfence();
        unsigned cnt = g_cnt_pad[tid * 32];
        s_h[tid] = cnt;          // reuse smem as count table
        __syncthreads();
        unsigned r = 0;
        #pragma unroll 8
        for (int j = 0; j < 256; j++) r += (s_h[j] < cnt) ? 1u : 0u;
        g_packed[tid] = (r << 8) | (unsigned)tid;
        g_cnt_pad[tid * 32] = 0u;
        if (tid == 0) g_ticket = 0u;
    }
}

// ---------------------------------------------------------------------------
// Kernel 2: entropy pool, full-width 16-row strips, u16 rank-packed tile.
// Phase 1: contiguous float4 slab (__ldcs, L2-resident), 4 table lookups,
//          pack 4 u16 -> STS.64 (tile stride 260 u16).
// Phase 2: thread = (rg in {0,1} x 8 rows, cg = column pair 2cg,2cg+1).
//          Per input row: 2 x LDS.32 -> 4 u16 -> both horizontal 3-mins
//          (1 wf per 32 cols, 3x fewer than scalar); rolling vertical 3-min.
//          Compare on rank (w>>8), strict '<' in row-then-col order ==
//          jnp.argmin first-occurrence (equal counts -> equal rank).
//          Stores: contiguous float2 (8B-aligned: row stride 1016 B).
//          Overreads (pad cols 256..259 / rows >= rows_in) feed only
//          discarded outputs.
// ---------------------------------------------------------------------------
__global__ void __launch_bounds__(256) pool_kernel(const float* __restrict__ x,
                                                   float* __restrict__ out) {
    __shared__ unsigned s_tbl[256];
    __shared__ unsigned short s16[PROWS * WP16];   // 9360 u16 = 18.3 KB

    const int tid = threadIdx.x;
    s_tbl[tid] = g_packed[tid];
    __syncthreads();

    const int plane = blockIdx.y;
    const int r0 = blockIdx.x * PTH;
    const int nout = min(PTH, HO - r0);
    const int rows_in = nout + 2;

    const float4* xp4 = (const float4*)(x + (size_t)plane * (H * W));
    const int base4 = r0 * (W / 4);
    const int n4 = rows_in * (W / 4);

    for (int i = tid; i < n4; i += 256) {
        float4 v = __ldcs(xp4 + base4 + i);
        unsigned p0 = s_tbl[((int)v.x) & 255];
        unsigned p1 = s_tbl[((int)v.y) & 255];
        unsigned p2 = s_tbl[((int)v.z) & 255];
        unsigned p3 = s_tbl[((int)v.w) & 255];
        uint2 pk;
        pk.x = p0 | (p1 << 16);
        pk.y = p2 | (p3 << 16);
        const int row = i >> 6, c4 = (i & 63) * 4;
        *(uint2*)&s16[row * WP16 + c4] = pk;
    }
    __syncthreads();

    const int cg = tid & 127;        // column pair: cols 2cg, 2cg+1
    const int rg = tid >> 7;         // 0/1 -> out rows 8rg..8rg+7
    const int c0 = 2 * cg;
    const int lr0 = rg * 8;

    if (c0 >= WO) return;            // cg==127: cols 254,255 both invalid

    auto hrow = [&](int lr, unsigned& m0, unsigned& m1) {
        unsigned A = *(const unsigned*)&s16[lr * WP16 + c0];      // cols c0,c0+1
        unsigned B = *(const unsigned*)&s16[lr * WP16 + c0 + 2];  // cols c0+2,c0+3
        unsigned w0 = A & 0xFFFFu, w1 = A >> 16;
        unsigned w2 = B & 0xFFFFu, w3 = B >> 16;
        m0 = w0; if ((w1 >> 8) < (m0 >> 8)) m0 = w1; if ((w2 >> 8) < (m0 >> 8)) m0 = w2;
        m1 = w1; if ((w2 >> 8) < (m1 >> 8)) m1 = w2; if ((w3 >> 8) < (m1 >> 8)) m1 = w3;
    };

    unsigned a0, a1, b0, b1, e0, e1;
    hrow(lr0 + 0, a0, a1);
    hrow(lr0 + 1, b0, b1);

    float* op = out + (size_t)plane * (HO * WO);
    #pragma unroll
    for (int k = 0; k < 8; k++) {
        const int orow = r0 + lr0 + k;
        if (orow >= HO) break;
        hrow(lr0 + k + 2, e0, e1);
        unsigned q0 = a0; if ((b0 >> 8) < (q0 >> 8)) q0 = b0; if ((e0 >> 8) < (q0 >> 8)) q0 = e0;
        unsigned q1 = a1; if ((b1 >> 8) < (q1 >> 8)) q1 = b1; if ((e1 >> 8) < (q1 >> 8)) q1 = e1;
        float2 o;
        o.x = (float)(q0 & 0xFFu);
        o.y = (float)(q1 & 0xFFu);
        *(float2*)&op[(size_t)orow * WO + c0] = o;
        a0 = b0; a1 = b1; b0 = e0; b1 = e1;
    }
}

// ---------------------------------------------------------------------------
extern "C" void kernel_launch(void* const* d_in, const int* in_sizes, int n_in,
                              void* d_out, int out_size) {
    const float* x = (const float*)d_in[0];
    float* out = (float*)d_out;

    hist_kernel<<<HB, HTH>>>(x);

    dim3 grid((HO + PTH - 1) / PTH, PLANES);   // (16, 256) = 4096 blocks
    pool_kernel<<<grid, 256>>>(x, out);
}